// round 6
// baseline (speedup 1.0000x reference)
#include <cuda_runtime.h>
#include <cuda_bf16.h>
#include <math.h>
#include <stdint.h>

#define N_SEQ   4096
#define DMODEL  1024
#define HEADS   8
#define DH      64
#define DINNER  512
#define QKVC    1536
#define WIN     128
#define NPERSIST 4

// ---------------- scratch (device globals; allocation-free rule) ------------
__device__ float g_qkv[N_SEQ * QKVC];
__device__ __nv_bfloat16 g_a_hi[N_SEQ * DMODEL];
__device__ __nv_bfloat16 g_a_lo[N_SEQ * DMODEL];
__device__ __nv_bfloat16 g_wqkvT_hi[QKVC * DMODEL];
__device__ __nv_bfloat16 g_wqkvT_lo[QKVC * DMODEL];
__device__ __nv_bfloat16 g_woutT_hi[DMODEL * DINNER];
__device__ __nv_bfloat16 g_woutT_lo[DMODEL * DINNER];
__device__ __nv_bfloat16 g_attn_hi[N_SEQ * DINNER];
__device__ __nv_bfloat16 g_attn_lo[N_SEQ * DINNER];

// ---------------- helpers ----------------------------------------------
__device__ __forceinline__ uint32_t smem_u32(const void* p) {
    uint32_t a;
    asm("{ .reg .u64 t; cvta.to.shared.u64 t, %1; cvt.u32.u64 %0, t; }" : "=r"(a) : "l"(p));
    return a;
}
__device__ __forceinline__ void cp_async16(uint32_t dst, const void* src) {
    asm volatile("cp.async.cg.shared.global [%0], [%1], 16;" :: "r"(dst), "l"(src));
}
__device__ __forceinline__ void cp_commit() {
    asm volatile("cp.async.commit_group;" ::: "memory");
}
template <int N>
__device__ __forceinline__ void cp_wait() {
    asm volatile("cp.async.wait_group %0;" :: "n"(N) : "memory");
}
__device__ __forceinline__ void ldm_x4(uint32_t& r0, uint32_t& r1, uint32_t& r2,
                                       uint32_t& r3, uint32_t addr) {
    asm volatile("ldmatrix.sync.aligned.m8n8.x4.shared.b16 {%0,%1,%2,%3}, [%4];"
                 : "=r"(r0), "=r"(r1), "=r"(r2), "=r"(r3) : "r"(addr));
}
__device__ __forceinline__ void mma_bf16(float* d, const uint32_t* a, const uint32_t* b) {
    asm volatile("mma.sync.aligned.m16n8k16.row.col.f32.bf16.bf16.f32 "
                 "{%0,%1,%2,%3}, {%4,%5,%6,%7}, {%8,%9}, {%0,%1,%2,%3};"
                 : "+f"(d[0]), "+f"(d[1]), "+f"(d[2]), "+f"(d[3])
                 : "r"(a[0]), "r"(a[1]), "r"(a[2]), "r"(a[3]), "r"(b[0]), "r"(b[1]));
}

// ---------------------------------------------------------------------------
// RMSNorm -> bf16 hi/lo
// ---------------------------------------------------------------------------
__global__ void rmsnorm_cvt_kernel(const float* __restrict__ seq,
                                   const float* __restrict__ g,
                                   __nv_bfloat16* __restrict__ hi,
                                   __nv_bfloat16* __restrict__ lo) {
    int row = blockIdx.x;
    int t = threadIdx.x;
    float4 v = ((const float4*)(seq + row * DMODEL))[t];
    float ss = v.x * v.x + v.y * v.y + v.z * v.z + v.w * v.w;
#pragma unroll
    for (int o = 16; o > 0; o >>= 1) ss += __shfl_xor_sync(0xffffffffu, ss, o);
    __shared__ float ws[8];
    if ((t & 31) == 0) ws[t >> 5] = ss;
    __syncthreads();
    float tot = ws[0] + ws[1] + ws[2] + ws[3] + ws[4] + ws[5] + ws[6] + ws[7];
    float inv = rsqrtf(tot * (1.0f / (float)DMODEL) + 1.1920929e-07f);
    float4 gv = ((const float4*)g)[t];
    float x0 = v.x * inv * gv.x, x1 = v.y * inv * gv.y;
    float x2 = v.z * inv * gv.z, x3 = v.w * inv * gv.w;
    size_t base = (size_t)row * DMODEL + t * 4;
    __nv_bfloat16 h0 = __float2bfloat16(x0), h1 = __float2bfloat16(x1);
    __nv_bfloat16 h2 = __float2bfloat16(x2), h3 = __float2bfloat16(x3);
    __nv_bfloat162 hp0; hp0.x = h0; hp0.y = h1;
    __nv_bfloat162 hp1; hp1.x = h2; hp1.y = h3;
    *(__nv_bfloat162*)(hi + base) = hp0;
    *(__nv_bfloat162*)(hi + base + 2) = hp1;
    __nv_bfloat162 lp0, lp1;
    lp0.x = __float2bfloat16(x0 - __bfloat162float(h0));
    lp0.y = __float2bfloat16(x1 - __bfloat162float(h1));
    lp1.x = __float2bfloat16(x2 - __bfloat162float(h2));
    lp1.y = __float2bfloat16(x3 - __bfloat162float(h3));
    *(__nv_bfloat162*)(lo + base) = lp0;
    *(__nv_bfloat162*)(lo + base + 2) = lp1;
}

// ---------------------------------------------------------------------------
// Transpose + bf16 hi/lo split: src[K][N] -> dst[N][K]
// ---------------------------------------------------------------------------
__global__ void transpose_cvt_kernel(const float* __restrict__ src, int K, int N,
                                     __nv_bfloat16* __restrict__ hi,
                                     __nv_bfloat16* __restrict__ lo) {
    __shared__ float tile[32][33];
    int bx = blockIdx.x, by = blockIdx.y;
    int tx = threadIdx.x, ty = threadIdx.y;
#pragma unroll
    for (int i = 0; i < 4; i++) {
        int k = by * 32 + ty + 8 * i;
        int n = bx * 32 + tx;
        tile[ty + 8 * i][tx] = src[(size_t)k * N + n];
    }
    __syncthreads();
#pragma unroll
    for (int i = 0; i < 4; i++) {
        int n = bx * 32 + ty + 8 * i;
        int k = by * 32 + tx;
        float v = tile[tx][ty + 8 * i];
        __nv_bfloat16 h = __float2bfloat16(v);
        hi[(size_t)n * K + k] = h;
        lo[(size_t)n * K + k] = __float2bfloat16(v - __bfloat162float(h));
    }
}

// ---------------------------------------------------------------------------
// Split-bf16 GEMM via mma.sync (HMMA). BK=32, SMEM 64KB -> 2 CTAs/SM.
// Rows are 64B; swizzle over 2-row 128B atoms:
//   phys(r,u) = (r>>1)*128 + ((((r&1)*4)+u) ^ ((r>>1)&7))*16,  u in 0..3
// ---------------------------------------------------------------------------
#define GEMM_SMEM (2 * 4 * 8192)
#define GSW(r, u) (((r) >> 1) * 128 + (((((r) & 1) * 4 + (u)) ^ (((r) >> 1) & 7)) << 4))

__global__ __launch_bounds__(256, 2)
void gemm_sb16_kernel(const __nv_bfloat16* __restrict__ Ahi,
                      const __nv_bfloat16* __restrict__ Alo,
                      const __nv_bfloat16* __restrict__ Bhi,
                      const __nv_bfloat16* __restrict__ Blo,
                      float* __restrict__ C, int K, int ldc) {
    extern __shared__ char smem[];
    uint32_t sb = smem_u32(smem);
    int tid = threadIdx.x;
    int wid = tid >> 5, lane = tid & 31;
    int m0 = blockIdx.y * 128, n0 = blockIdx.x * 128;
    int wm = wid & 1;
    int wn = wid >> 1;

    // prefetch K-chunk c (32 wide) into buffer buf; 8KB per array
    auto prefetch = [&](int c, int buf) {
        int kc = c << 5;
        uint32_t b32 = sb + buf * 32768;
#pragma unroll
        for (int i = 0; i < 2; i++) {
            int idx = tid + 256 * i;
            int r = idx >> 2, u = idx & 3;
            uint32_t dst = b32 + GSW(r, u);
            size_t ga = (size_t)(m0 + r) * K + kc + u * 8;
            size_t gb = (size_t)(n0 + r) * K + kc + u * 8;
            cp_async16(dst,         Ahi + ga);
            cp_async16(dst + 8192,  Alo + ga);
            cp_async16(dst + 16384, Bhi + gb);
            cp_async16(dst + 24576, Blo + gb);
        }
        cp_commit();
    };

    float acc[4][4][4];
#pragma unroll
    for (int i = 0; i < 4; i++)
#pragma unroll
        for (int j = 0; j < 4; j++)
#pragma unroll
            for (int k = 0; k < 4; k++) acc[i][j][k] = 0.f;

    int NC = K >> 5;
    prefetch(0, 0);

    for (int c = 0; c < NC; c++) {
        int buf = c & 1;
        if (c + 1 < NC) {
            prefetch(c + 1, buf ^ 1);
            cp_wait<1>();
        } else {
            cp_wait<0>();
        }
        __syncthreads();

        uint32_t b32 = sb + buf * 32768;
#pragma unroll
        for (int ks = 0; ks < 2; ks++) {
            uint32_t ah[4][4], al[4][4], bh[4][2], bl[4][2];
            int u = 2 * ks + (lane >> 4);
#pragma unroll
            for (int mt = 0; mt < 4; mt++) {
                int r = wm * 64 + mt * 16 + (lane & 15);
                uint32_t addr = b32 + GSW(r, u);
                ldm_x4(ah[mt][0], ah[mt][1], ah[mt][2], ah[mt][3], addr);
                ldm_x4(al[mt][0], al[mt][1], al[mt][2], al[mt][3], addr + 8192);
            }
#pragma unroll
            for (int np = 0; np < 2; np++) {
                int r = wn * 32 + np * 16 + (lane & 15);
                uint32_t addr = b32 + 16384 + GSW(r, u);
                uint32_t t0, t1, t2, t3;
                ldm_x4(t0, t1, t2, t3, addr);
                bh[2 * np][0] = t0; bh[2 * np][1] = t2;
                bh[2 * np + 1][0] = t1; bh[2 * np + 1][1] = t3;
                ldm_x4(t0, t1, t2, t3, addr + 8192);
                bl[2 * np][0] = t0; bl[2 * np][1] = t2;
                bl[2 * np + 1][0] = t1; bl[2 * np + 1][1] = t3;
            }
#pragma unroll
            for (int mt = 0; mt < 4; mt++)
#pragma unroll
                for (int nt = 0; nt < 4; nt++) {
                    mma_bf16(acc[mt][nt], ah[mt], bh[nt]);
                    mma_bf16(acc[mt][nt], ah[mt], bl[nt]);
                    mma_bf16(acc[mt][nt], al[mt], bh[nt]);
                }
        }
        __syncthreads();
    }

    int rbase = m0 + wm * 64 + (lane >> 2);
    int cbase = n0 + wn * 32 + (lane & 3) * 2;
#pragma unroll
    for (int mt = 0; mt < 4; mt++)
#pragma unroll
        for (int nt = 0; nt < 4; nt++) {
            int row = rbase + mt * 16;
            int col = cbase + nt * 8;
            float2 v0 = make_float2(acc[mt][nt][0], acc[mt][nt][1]);
            float2 v1 = make_float2(acc[mt][nt][2], acc[mt][nt][3]);
            *(float2*)(C + (size_t)row * ldc + col) = v0;
            *(float2*)(C + (size_t)(row + 8) * ldc + col) = v1;
        }
}

// ---------------------------------------------------------------------------
// RoPE (interleaved pairs), in place on q,k of fp32 qkv
// ---------------------------------------------------------------------------
__global__ void rope_kernel(float* __restrict__ qkv) {
    int idx = blockIdx.x * blockDim.x + threadIdx.x;
    if (idx >= N_SEQ * 256) return;
    int n = idx >> 8;
    int p = idx & 255;
    int t = p & 31;
    float inv = (float)exp(-(double)t * (9.210340371976184 / 32.0));
    float ang = (float)n * inv;
    float s, c;
    sincosf(ang, &s, &c);
    float* q = qkv + (size_t)n * QKVC + 2 * p;
    float q0 = q[0], q1 = q[1];
    q[0] = q0 * c - q1 * s;
    q[1] = q1 * c + q0 * s;
    float* k = q + DINNER;
    float k0 = k[0], k1 = k[1];
    k[0] = k0 * c - k1 * s;
    k[1] = k1 * c + k0 * s;
}

// ---------------------------------------------------------------------------
// Fused sliding-window attention -> bf16 hi/lo output.
// ---------------------------------------------------------------------------
#define MAX_KEYS 196
#define ATTN_SMEM (2 * MAX_KEYS * 64 * 4)
#define SW(r, u) ((u) ^ (((u) & 8) >> 1) ^ ((r) & 7))

__global__ __launch_bounds__(128) void attn_kernel(const float* __restrict__ qkv,
                                                   __nv_bfloat16* __restrict__ out_hi,
                                                   __nv_bfloat16* __restrict__ out_lo) {
    extern __shared__ float smemf[];
    float4* Ks = (float4*)smemf;
    float4* Vs = (float4*)(smemf + MAX_KEYS * 64);

    int h = blockIdx.y;
    int qs = blockIdx.x * 64;
    int tid = threadIdx.x;

    int kv_lo = qs - WIN; if (kv_lo < 0) kv_lo = 0;
    int cnt = qs + 64 - kv_lo;
    int P = (kv_lo > 0) ? NPERSIST : 0;
    int tot = cnt + P;

    for (int idx = tid; idx < tot * 16; idx += 128) {
        int r = idx >> 4;
        int u = idx & 15;
        int gk = (r < cnt) ? (kv_lo + r) : (r - cnt);
        const float* base = qkv + (size_t)gk * QKVC + h * DH + u * 4;
        int su = r * 16 + SW(r, u);
        Ks[su] = *(const float4*)(base + DINNER);
        Vs[su] = *(const float4*)(base + 2 * DINNER);
    }
    __syncthreads();

    int lq = tid >> 1;
    int half = tid & 1;
    int qidx = qs + lq;
    int lane = tid & 31;
    unsigned pairmask = 0x3u << (lane & 30);
    int ub = half * 8;

    float q[32], o[32];
    const float4* q4 = (const float4*)(qkv + (size_t)qidx * QKVC + h * DH + half * 32);
#pragma unroll
    for (int i = 0; i < 8; i++) {
        float4 v = q4[i];
        q[4 * i] = v.x; q[4 * i + 1] = v.y; q[4 * i + 2] = v.z; q[4 * i + 3] = v.w;
        o[4 * i] = 0.f; o[4 * i + 1] = 0.f; o[4 * i + 2] = 0.f; o[4 * i + 3] = 0.f;
    }

    float m = -INFINITY, l = 0.f;

    auto chunk4 = [&](int r0, int r1, int r2, int r3,
                      bool v1ok, bool v2ok, bool v3ok) {
        float a0 = 0.f, b0 = 0.f, a1 = 0.f, b1 = 0.f;
        float a2 = 0.f, b2 = 0.f, a3 = 0.f, b3 = 0.f;
#pragma unroll
        for (int i = 0; i < 8; i++) {
            float4 x0 = Ks[r0 * 16 + SW(r0, ub + i)];
            float4 x1 = Ks[r1 * 16 + SW(r1, ub + i)];
            float4 x2 = Ks[r2 * 16 + SW(r2, ub + i)];
            float4 x3 = Ks[r3 * 16 + SW(r3, ub + i)];
            float q0 = q[4 * i], q1 = q[4 * i + 1], q2 = q[4 * i + 2], q3 = q[4 * i + 3];
            if (i & 1) {
                b0 = fmaf(q0, x0.x, b0); b0 = fmaf(q1, x0.y, b0);
                b0 = fmaf(q2, x0.z, b0); b0 = fmaf(q3, x0.w, b0);
                b1 = fmaf(q0, x1.x, b1); b1 = fmaf(q1, x1.y, b1);
                b1 = fmaf(q2, x1.z, b1); b1 = fmaf(q3, x1.w, b1);
                b2 = fmaf(q0, x2.x, b2); b2 = fmaf(q1, x2.y, b2);
                b2 = fmaf(q2, x2.z, b2); b2 = fmaf(q3, x2.w, b2);
                b3 = fmaf(q0, x3.x, b3); b3 = fmaf(q1, x3.y, b3);
                b3 = fmaf(q2, x3.z, b3); b3 = fmaf(q3, x3.w, b3);
            } else {
                a0 = fmaf(q0, x0.x, a0); a0 = fmaf(q1, x0.y, a0);
                a0 = fmaf(q2, x0.z, a0); a0 = fmaf(q3, x0.w, a0);
                a1 = fmaf(q0, x1.x, a1); a1 = fmaf(q1, x1.y, a1);
                a1 = fmaf(q2, x1.z, a1); a1 = fmaf(q3, x1.w, a1);
                a2 = fmaf(q0, x2.x, a2); a2 = fmaf(q1, x2.y, a2);
                a2 = fmaf(q2, x2.z, a2); a2 = fmaf(q3, x2.w, a2);
                a3 = fmaf(q0, x3.x, a3); a3 = fmaf(q1, x3.y, a3);
                a3 = fmaf(q2, x3.z, a3); a3 = fmaf(q3, x3.w, a3);
            }
        }
        float s0 = a0 + b0, s1 = a1 + b1, s2 = a2 + b2, s3 = a3 + b3;
        s0 += __shfl_xor_sync(pairmask, s0, 1);
        s1 += __shfl_xor_sync(pairmask, s1, 1);
        s2 += __shfl_xor_sync(pairmask, s2, 1);
        s3 += __shfl_xor_sync(pairmask, s3, 1);
        s0 *= 0.125f; s1 *= 0.125f; s2 *= 0.125f; s3 *= 0.125f;
        if (!v1ok) s1 = -INFINITY;
        if (!v2ok) s2 = -INFINITY;
        if (!v3ok) s3 = -INFINITY;

        float mn = fmaxf(m, fmaxf(fmaxf(s0, s1), fmaxf(s2, s3)));
        float corr = __expf(m - mn);
        float p0 = __expf(s0 - mn);
        float p1 = __expf(s1 - mn);
        float p2 = __expf(s2 - mn);
        float p3 = __expf(s3 - mn);
        l = l * corr + ((p0 + p1) + (p2 + p3));
        m = mn;

#pragma unroll
        for (int i = 0; i < 8; i++) {
            float4 y0 = Vs[r0 * 16 + SW(r0, ub + i)];
            float4 y1 = Vs[r1 * 16 + SW(r1, ub + i)];
            float4 y2 = Vs[r2 * 16 + SW(r2, ub + i)];
            float4 y3 = Vs[r3 * 16 + SW(r3, ub + i)];
            float t0 = o[4 * i] * corr;
            float t1 = o[4 * i + 1] * corr;
            float t2 = o[4 * i + 2] * corr;
            float t3 = o[4 * i + 3] * corr;
            t0 = fmaf(p0, y0.x, t0); t1 = fmaf(p0, y0.y, t1);
            t2 = fmaf(p0, y0.z, t2); t3 = fmaf(p0, y0.w, t3);
            t0 = fmaf(p1, y1.x, t0); t1 = fmaf(p1, y1.y, t1);
            t2 = fmaf(p1, y1.z, t2); t3 = fmaf(p1, y1.w, t3);
            t0 = fmaf(p2, y2.x, t0); t1 = fmaf(p2, y2.y, t1);
            t2 = fmaf(p2, y2.z, t2); t3 = fmaf(p2, y2.w, t3);
            t0 = fmaf(p3, y3.x, t0); t1 = fmaf(p3, y3.y, t1);
            t2 = fmaf(p3, y3.z, t2); t3 = fmaf(p3, y3.w, t3);
            o[4 * i] = t0; o[4 * i + 1] = t1; o[4 * i + 2] = t2; o[4 * i + 3] = t3;
        }
    };

    int jlo = qidx - WIN - kv_lo; if (jlo < 0) jlo = 0;
    int jhi = qidx - kv_lo;
    int covered_lo = kv_lo + jlo;

    if (covered_lo > 0) {
        int base = (kv_lo > 0) ? cnt : 0;
        chunk4(base + 0, base + 1, base + 2, base + 3,
               1 < covered_lo && 1 < NPERSIST,
               2 < covered_lo && 2 < NPERSIST,
               3 < covered_lo && 3 < NPERSIST);
    }

    int j = jlo;
    for (; j + 3 <= jhi; j += 4) chunk4(j, j + 1, j + 2, j + 3, true, true, true);
    int rem = jhi - j + 1;
    if (rem > 0) {
        int r1 = (rem > 1) ? j + 1 : j;
        int r2 = (rem > 2) ? j + 2 : j;
        chunk4(j, r1, r2, j, rem > 1, rem > 2, false);
    }

    float invl = 1.0f / l;
    size_t obase = (size_t)qidx * DINNER + h * DH + half * 32;
#pragma unroll
    for (int i = 0; i < 8; i++) {
        float v0 = o[4 * i] * invl;
        float v1 = o[4 * i + 1] * invl;
        float v2 = o[4 * i + 2] * invl;
        float v3 = o[4 * i + 3] * invl;
        __nv_bfloat16 h0 = __float2bfloat16(v0), h1 = __float2bfloat16(v1);
        __nv_bfloat16 h2 = __float2bfloat16(v2), h3 = __float2bfloat16(v3);
        __nv_bfloat162 hp0; hp0.x = h0; hp0.y = h1;
        __nv_bfloat162 hp1; hp1.x = h2; hp1.y = h3;
        *(__nv_bfloat162*)(out_hi + obase + 4 * i) = hp0;
        *(__nv_bfloat162*)(out_hi + obase + 4 * i + 2) = hp1;
        __nv_bfloat162 lp0, lp1;
        lp0.x = __float2bfloat16(v0 - __bfloat162float(h0));
        lp0.y = __float2bfloat16(v1 - __bfloat162float(h1));
        lp1.x = __float2bfloat16(v2 - __bfloat162float(h2));
        lp1.y = __float2bfloat16(v3 - __bfloat162float(h3));
        *(__nv_bfloat162*)(out_lo + obase + 4 * i) = lp0;
        *(__nv_bfloat162*)(out_lo + obase + 4 * i + 2) = lp1;
    }
}

// ---------------------------------------------------------------------------
extern "C" void kernel_launch(void* const* d_in, const int* in_sizes, int n_in,
                              void* d_out, int out_size) {
    const float* seq   = (const float*)d_in[0];
    const float* g     = (const float*)d_in[1];
    const float* w_qkv = (const float*)d_in[2];
    const float* w_out = (const float*)d_in[3];
    float* out = (float*)d_out;

    float* qkvp;
    __nv_bfloat16 *ahi, *alo, *wqh, *wql, *woh, *wol, *athi, *atlo;
    cudaGetSymbolAddress((void**)&qkvp, g_qkv);
    cudaGetSymbolAddress((void**)&ahi, g_a_hi);
    cudaGetSymbolAddress((void**)&alo, g_a_lo);
    cudaGetSymbolAddress((void**)&wqh, g_wqkvT_hi);
    cudaGetSymbolAddress((void**)&wql, g_wqkvT_lo);
    cudaGetSymbolAddress((void**)&woh, g_woutT_hi);
    cudaGetSymbolAddress((void**)&wol, g_woutT_lo);
    cudaGetSymbolAddress((void**)&athi, g_attn_hi);
    cudaGetSymbolAddress((void**)&atlo, g_attn_lo);

    cudaFuncSetAttribute(attn_kernel, cudaFuncAttributeMaxDynamicSharedMemorySize,
                         ATTN_SMEM);
    cudaFuncSetAttribute(gemm_sb16_kernel, cudaFuncAttributeMaxDynamicSharedMemorySize,
                         GEMM_SMEM);

    rmsnorm_cvt_kernel<<<N_SEQ, 256>>>(seq, g, ahi, alo);
    transpose_cvt_kernel<<<dim3(QKVC / 32, DMODEL / 32), dim3(32, 8)>>>(
        w_qkv, DMODEL, QKVC, wqh, wql);
    transpose_cvt_kernel<<<dim3(DMODEL / 32, DINNER / 32), dim3(32, 8)>>>(
        w_out, DINNER, DMODEL, woh, wol);

    gemm_sb16_kernel<<<dim3(QKVC / 128, N_SEQ / 128), 256, GEMM_SMEM>>>(
        ahi, alo, wqh, wql, qkvp, DMODEL, QKVC);

    rope_kernel<<<(N_SEQ * 256 + 255) / 256, 256>>>(qkvp);
    attn_kernel<<<dim3(N_SEQ / 64, HEADS), 128, ATTN_SMEM>>>(qkvp, athi, atlo);

    gemm_sb16_kernel<<<dim3(DMODEL / 128, N_SEQ / 128), 256, GEMM_SMEM>>>(
        athi, atlo, woh, wol, out, DINNER, DMODEL);
}

// round 8
// speedup vs baseline: 1.0918x; 1.0918x over previous
#include <cuda_runtime.h>
#include <cuda_bf16.h>
#include <math.h>
#include <stdint.h>

#define N_SEQ   4096
#define DMODEL  1024
#define HEADS   8
#define DH      64
#define DINNER  512
#define QKVC    1536
#define WIN     128
#define NPERSIST 4

// ---------------- scratch (device globals; allocation-free rule) ------------
__device__ float g_qkv[N_SEQ * QKVC];
__device__ __nv_bfloat16 g_a_hi[N_SEQ * DMODEL];
__device__ __nv_bfloat16 g_a_lo[N_SEQ * DMODEL];
__device__ __nv_bfloat16 g_wqkvT_hi[QKVC * DMODEL];
__device__ __nv_bfloat16 g_wqkvT_lo[QKVC * DMODEL];
__device__ __nv_bfloat16 g_woutT_hi[DMODEL * DINNER];
__device__ __nv_bfloat16 g_woutT_lo[DMODEL * DINNER];
__device__ __nv_bfloat16 g_attn_hi[N_SEQ * DINNER];
__device__ __nv_bfloat16 g_attn_lo[N_SEQ * DINNER];

// ---------------- helpers ----------------------------------------------
__device__ __forceinline__ uint32_t smem_u32(const void* p) {
    uint32_t a;
    asm("{ .reg .u64 t; cvta.to.shared.u64 t, %1; cvt.u32.u64 %0, t; }" : "=r"(a) : "l"(p));
    return a;
}
__device__ __forceinline__ void cp_async16(uint32_t dst, const void* src) {
    asm volatile("cp.async.cg.shared.global [%0], [%1], 16;" :: "r"(dst), "l"(src));
}
__device__ __forceinline__ void cp_commit() {
    asm volatile("cp.async.commit_group;" ::: "memory");
}
template <int N>
__device__ __forceinline__ void cp_wait() {
    asm volatile("cp.async.wait_group %0;" :: "n"(N) : "memory");
}
__device__ __forceinline__ void ldm_x4(uint32_t& r0, uint32_t& r1, uint32_t& r2,
                                       uint32_t& r3, uint32_t addr) {
    asm volatile("ldmatrix.sync.aligned.m8n8.x4.shared.b16 {%0,%1,%2,%3}, [%4];"
                 : "=r"(r0), "=r"(r1), "=r"(r2), "=r"(r3) : "r"(addr));
}
__device__ __forceinline__ void mma_bf16(float* d, const uint32_t* a, const uint32_t* b) {
    asm volatile("mma.sync.aligned.m16n8k16.row.col.f32.bf16.bf16.f32 "
                 "{%0,%1,%2,%3}, {%4,%5,%6,%7}, {%8,%9}, {%0,%1,%2,%3};"
                 : "+f"(d[0]), "+f"(d[1]), "+f"(d[2]), "+f"(d[3])
                 : "r"(a[0]), "r"(a[1]), "r"(a[2]), "r"(a[3]), "r"(b[0]), "r"(b[1]));
}

// ---------------------------------------------------------------------------
// RMSNorm -> bf16 hi/lo
// ---------------------------------------------------------------------------
__global__ void rmsnorm_cvt_kernel(const float* __restrict__ seq,
                                   const float* __restrict__ g,
                                   __nv_bfloat16* __restrict__ hi,
                                   __nv_bfloat16* __restrict__ lo) {
    int row = blockIdx.x;
    int t = threadIdx.x;
    float4 v = ((const float4*)(seq + row * DMODEL))[t];
    float ss = v.x * v.x + v.y * v.y + v.z * v.z + v.w * v.w;
#pragma unroll
    for (int o = 16; o > 0; o >>= 1) ss += __shfl_xor_sync(0xffffffffu, ss, o);
    __shared__ float ws[8];
    if ((t & 31) == 0) ws[t >> 5] = ss;
    __syncthreads();
    float tot = ws[0] + ws[1] + ws[2] + ws[3] + ws[4] + ws[5] + ws[6] + ws[7];
    float inv = rsqrtf(tot * (1.0f / (float)DMODEL) + 1.1920929e-07f);
    float4 gv = ((const float4*)g)[t];
    float x0 = v.x * inv * gv.x, x1 = v.y * inv * gv.y;
    float x2 = v.z * inv * gv.z, x3 = v.w * inv * gv.w;
    size_t base = (size_t)row * DMODEL + t * 4;
    __nv_bfloat16 h0 = __float2bfloat16(x0), h1 = __float2bfloat16(x1);
    __nv_bfloat16 h2 = __float2bfloat16(x2), h3 = __float2bfloat16(x3);
    __nv_bfloat162 hp0; hp0.x = h0; hp0.y = h1;
    __nv_bfloat162 hp1; hp1.x = h2; hp1.y = h3;
    *(__nv_bfloat162*)(hi + base) = hp0;
    *(__nv_bfloat162*)(hi + base + 2) = hp1;
    __nv_bfloat162 lp0, lp1;
    lp0.x = __float2bfloat16(x0 - __bfloat162float(h0));
    lp0.y = __float2bfloat16(x1 - __bfloat162float(h1));
    lp1.x = __float2bfloat16(x2 - __bfloat162float(h2));
    lp1.y = __float2bfloat16(x3 - __bfloat162float(h3));
    *(__nv_bfloat162*)(lo + base) = lp0;
    *(__nv_bfloat162*)(lo + base + 2) = lp1;
}

// ---------------------------------------------------------------------------
// Transpose + bf16 hi/lo split: src[K][N] -> dst[N][K]
// ---------------------------------------------------------------------------
__global__ void transpose_cvt_kernel(const float* __restrict__ src, int K, int N,
                                     __nv_bfloat16* __restrict__ hi,
                                     __nv_bfloat16* __restrict__ lo) {
    __shared__ float tile[32][33];
    int bx = blockIdx.x, by = blockIdx.y;
    int tx = threadIdx.x, ty = threadIdx.y;
#pragma unroll
    for (int i = 0; i < 4; i++) {
        int k = by * 32 + ty + 8 * i;
        int n = bx * 32 + tx;
        tile[ty + 8 * i][tx] = src[(size_t)k * N + n];
    }
    __syncthreads();
#pragma unroll
    for (int i = 0; i < 4; i++) {
        int n = bx * 32 + ty + 8 * i;
        int k = by * 32 + tx;
        float v = tile[tx][ty + 8 * i];
        __nv_bfloat16 h = __float2bfloat16(v);
        hi[(size_t)n * K + k] = h;
        lo[(size_t)n * K + k] = __float2bfloat16(v - __bfloat162float(h));
    }
}

// ---------------------------------------------------------------------------
// Split-bf16 GEMM via mma.sync (HMMA), BK=64, term-major MMA ordering
// (no accumulator RAW between consecutive MMAs). Optional fused RoPE epilogue:
// columns < rope_cols get interleaved-pair rotation at angle row*inv_freq.
// ---------------------------------------------------------------------------
#define GEMM_SMEM (2 * 4 * 16384)

struct Frag {
    uint32_t ah[4][4], al[4][4], bh[4][2], bl[4][2];
};

__global__ __launch_bounds__(256, 1)
void gemm_sb16_kernel(const __nv_bfloat16* __restrict__ Ahi,
                      const __nv_bfloat16* __restrict__ Alo,
                      const __nv_bfloat16* __restrict__ Bhi,
                      const __nv_bfloat16* __restrict__ Blo,
                      float* __restrict__ C, int K, int ldc, int rope_cols) {
    extern __shared__ char smem[];
    uint32_t sb = smem_u32(smem);
    int tid = threadIdx.x;
    int wid = tid >> 5, lane = tid & 31;
    int m0 = blockIdx.y * 128, n0 = blockIdx.x * 128;
    int wm = wid & 1;
    int wn = wid >> 1;

    auto prefetch = [&](int c, int buf) {
        int kc = c << 6;
        uint32_t b32 = sb + buf * 65536;
#pragma unroll
        for (int i = 0; i < 4; i++) {
            int idx = tid + 256 * i;
            int r = idx >> 3, u = idx & 7;
            uint32_t dst = b32 + r * 128 + ((u ^ (r & 7)) << 4);
            size_t ga = (size_t)(m0 + r) * K + kc + u * 8;
            size_t gb = (size_t)(n0 + r) * K + kc + u * 8;
            cp_async16(dst,         Ahi + ga);
            cp_async16(dst + 16384, Alo + ga);
            cp_async16(dst + 32768, Bhi + gb);
            cp_async16(dst + 49152, Blo + gb);
        }
        cp_commit();
    };

    auto load_frags = [&](uint32_t b32, int ks, Frag& f) {
#pragma unroll
        for (int mt = 0; mt < 4; mt++) {
            int r = wm * 64 + mt * 16 + (lane & 15);
            int u = 2 * ks + (lane >> 4);
            uint32_t addr = b32 + r * 128 + ((u ^ (r & 7)) << 4);
            ldm_x4(f.ah[mt][0], f.ah[mt][1], f.ah[mt][2], f.ah[mt][3], addr);
            ldm_x4(f.al[mt][0], f.al[mt][1], f.al[mt][2], f.al[mt][3], addr + 16384);
        }
#pragma unroll
        for (int np = 0; np < 2; np++) {
            int r = wn * 32 + np * 16 + (lane & 15);
            int u = 2 * ks + (lane >> 4);
            uint32_t addr = b32 + 32768 + r * 128 + ((u ^ (r & 7)) << 4);
            uint32_t t0, t1, t2, t3;
            ldm_x4(t0, t1, t2, t3, addr);
            f.bh[2 * np][0] = t0; f.bh[2 * np][1] = t2;
            f.bh[2 * np + 1][0] = t1; f.bh[2 * np + 1][1] = t3;
            ldm_x4(t0, t1, t2, t3, addr + 16384);   // Blo plane (+49152 total)
            f.bl[2 * np][0] = t0; f.bl[2 * np][1] = t2;
            f.bl[2 * np + 1][0] = t1; f.bl[2 * np + 1][1] = t3;
        }
    };

    float acc[4][4][4];
#pragma unroll
    for (int i = 0; i < 4; i++)
#pragma unroll
        for (int j = 0; j < 4; j++)
#pragma unroll
            for (int k = 0; k < 4; k++) acc[i][j][k] = 0.f;

    int NC = K >> 6;
    prefetch(0, 0);

    Frag f0, f1;
    for (int c = 0; c < NC; c++) {
        int buf = c & 1;
        if (c + 1 < NC) {
            prefetch(c + 1, buf ^ 1);
            cp_wait<1>();
        } else {
            cp_wait<0>();
        }
        __syncthreads();

        uint32_t b32 = sb + buf * 65536;
        load_frags(b32, 0, f0);
#pragma unroll
        for (int ks = 0; ks < 4; ks++) {
            Frag& cur = (ks & 1) ? f1 : f0;
            Frag& nxt = (ks & 1) ? f0 : f1;
            if (ks < 3) load_frags(b32, ks + 1, nxt);
            // term-major: consecutive MMAs hit distinct accumulators (no RAW)
#pragma unroll
            for (int mt = 0; mt < 4; mt++)
#pragma unroll
                for (int nt = 0; nt < 4; nt++)
                    mma_bf16(acc[mt][nt], cur.ah[mt], cur.bh[nt]);
#pragma unroll
            for (int mt = 0; mt < 4; mt++)
#pragma unroll
                for (int nt = 0; nt < 4; nt++)
                    mma_bf16(acc[mt][nt], cur.ah[mt], cur.bl[nt]);
#pragma unroll
            for (int mt = 0; mt < 4; mt++)
#pragma unroll
                for (int nt = 0; nt < 4; nt++)
                    mma_bf16(acc[mt][nt], cur.al[mt], cur.bh[nt]);
        }
        __syncthreads();
    }

    int rbase = m0 + wm * 64 + (lane >> 2);
    int cbase = n0 + wn * 32 + (lane & 3) * 2;

    // per-nt inv_freq for fused RoPE (pair index = (col & 63) >> 1)
    float invf[4];
    if (rope_cols > 0) {
#pragma unroll
        for (int nt = 0; nt < 4; nt++) {
            int t = ((cbase + nt * 8) & 63) >> 1;
            invf[nt] = (float)exp(-(double)t * (9.210340371976184 / 32.0));
        }
    }

#pragma unroll
    for (int mt = 0; mt < 4; mt++)
#pragma unroll
        for (int nt = 0; nt < 4; nt++) {
            int row = rbase + mt * 16;
            int col = cbase + nt * 8;
            float2 v0 = make_float2(acc[mt][nt][0], acc[mt][nt][1]);
            float2 v1 = make_float2(acc[mt][nt][2], acc[mt][nt][3]);
            if (col < rope_cols) {
                float s, cc;
                sincosf((float)row * invf[nt], &s, &cc);
                float a = v0.x, b = v0.y;
                v0.x = a * cc - b * s;
                v0.y = b * cc + a * s;
                sincosf((float)(row + 8) * invf[nt], &s, &cc);
                a = v1.x; b = v1.y;
                v1.x = a * cc - b * s;
                v1.y = b * cc + a * s;
            }
            *(float2*)(C + (size_t)row * ldc + col) = v0;
            *(float2*)(C + (size_t)(row + 8) * ldc + col) = v1;
        }
}

// ---------------------------------------------------------------------------
// Fused sliding-window attention -> bf16 hi/lo output.
// ---------------------------------------------------------------------------
#define MAX_KEYS 196
#define ATTN_SMEM (2 * MAX_KEYS * 64 * 4)
#define SW(r, u) ((u) ^ (((u) & 8) >> 1) ^ ((r) & 7))

__global__ __launch_bounds__(128) void attn_kernel(const float* __restrict__ qkv,
                                                   __nv_bfloat16* __restrict__ out_hi,
                                                   __nv_bfloat16* __restrict__ out_lo) {
    extern __shared__ float smemf[];
    float4* Ks = (float4*)smemf;
    float4* Vs = (float4*)(smemf + MAX_KEYS * 64);

    int h = blockIdx.y;
    int qs = blockIdx.x * 64;
    int tid = threadIdx.x;

    int kv_lo = qs - WIN; if (kv_lo < 0) kv_lo = 0;
    int cnt = qs + 64 - kv_lo;
    int P = (kv_lo > 0) ? NPERSIST : 0;
    int tot = cnt + P;

    for (int idx = tid; idx < tot * 16; idx += 128) {
        int r = idx >> 4;
        int u = idx & 15;
        int gk = (r < cnt) ? (kv_lo + r) : (r - cnt);
        const float* base = qkv + (size_t)gk * QKVC + h * DH + u * 4;
        int su = r * 16 + SW(r, u);
        Ks[su] = *(const float4*)(base + DINNER);
        Vs[su] = *(const float4*)(base + 2 * DINNER);
    }
    __syncthreads();

    int lq = tid >> 1;
    int half = tid & 1;
    int qidx = qs + lq;
    int lane = tid & 31;
    unsigned pairmask = 0x3u << (lane & 30);
    int ub = half * 8;

    float q[32], o[32];
    const float4* q4 = (const float4*)(qkv + (size_t)qidx * QKVC + h * DH + half * 32);
#pragma unroll
    for (int i = 0; i < 8; i++) {
        float4 v = q4[i];
        q[4 * i] = v.x; q[4 * i + 1] = v.y; q[4 * i + 2] = v.z; q[4 * i + 3] = v.w;
        o[4 * i] = 0.f; o[4 * i + 1] = 0.f; o[4 * i + 2] = 0.f; o[4 * i + 3] = 0.f;
    }

    float m = -INFINITY, l = 0.f;

    auto chunk4 = [&](int r0, int r1, int r2, int r3,
                      bool v1ok, bool v2ok, bool v3ok) {
        float a0 = 0.f, b0 = 0.f, a1 = 0.f, b1 = 0.f;
        float a2 = 0.f, b2 = 0.f, a3 = 0.f, b3 = 0.f;
#pragma unroll
        for (int i = 0; i < 8; i++) {
            float4 x0 = Ks[r0 * 16 + SW(r0, ub + i)];
            float4 x1 = Ks[r1 * 16 + SW(r1, ub + i)];
            float4 x2 = Ks[r2 * 16 + SW(r2, ub + i)];
            float4 x3 = Ks[r3 * 16 + SW(r3, ub + i)];
            float q0 = q[4 * i], q1 = q[4 * i + 1], q2 = q[4 * i + 2], q3 = q[4 * i + 3];
            if (i & 1) {
                b0 = fmaf(q0, x0.x, b0); b0 = fmaf(q1, x0.y, b0);
                b0 = fmaf(q2, x0.z, b0); b0 = fmaf(q3, x0.w, b0);
                b1 = fmaf(q0, x1.x, b1); b1 = fmaf(q1, x1.y, b1);
                b1 = fmaf(q2, x1.z, b1); b1 = fmaf(q3, x1.w, b1);
                b2 = fmaf(q0, x2.x, b2); b2 = fmaf(q1, x2.y, b2);
                b2 = fmaf(q2, x2.z, b2); b2 = fmaf(q3, x2.w, b2);
                b3 = fmaf(q0, x3.x, b3); b3 = fmaf(q1, x3.y, b3);
                b3 = fmaf(q2, x3.z, b3); b3 = fmaf(q3, x3.w, b3);
            } else {
                a0 = fmaf(q0, x0.x, a0); a0 = fmaf(q1, x0.y, a0);
                a0 = fmaf(q2, x0.z, a0); a0 = fmaf(q3, x0.w, a0);
                a1 = fmaf(q0, x1.x, a1); a1 = fmaf(q1, x1.y, a1);
                a1 = fmaf(q2, x1.z, a1); a1 = fmaf(q3, x1.w, a1);
                a2 = fmaf(q0, x2.x, a2); a2 = fmaf(q1, x2.y, a2);
                a2 = fmaf(q2, x2.z, a2); a2 = fmaf(q3, x2.w, a2);
                a3 = fmaf(q0, x3.x, a3); a3 = fmaf(q1, x3.y, a3);
                a3 = fmaf(q2, x3.z, a3); a3 = fmaf(q3, x3.w, a3);
            }
        }
        float s0 = a0 + b0, s1 = a1 + b1, s2 = a2 + b2, s3 = a3 + b3;
        s0 += __shfl_xor_sync(pairmask, s0, 1);
        s1 += __shfl_xor_sync(pairmask, s1, 1);
        s2 += __shfl_xor_sync(pairmask, s2, 1);
        s3 += __shfl_xor_sync(pairmask, s3, 1);
        s0 *= 0.125f; s1 *= 0.125f; s2 *= 0.125f; s3 *= 0.125f;
        if (!v1ok) s1 = -INFINITY;
        if (!v2ok) s2 = -INFINITY;
        if (!v3ok) s3 = -INFINITY;

        float mn = fmaxf(m, fmaxf(fmaxf(s0, s1), fmaxf(s2, s3)));
        float corr = __expf(m - mn);
        float p0 = __expf(s0 - mn);
        float p1 = __expf(s1 - mn);
        float p2 = __expf(s2 - mn);
        float p3 = __expf(s3 - mn);
        l = l * corr + ((p0 + p1) + (p2 + p3));
        m = mn;

#pragma unroll
        for (int i = 0; i < 8; i++) {
            float4 y0 = Vs[r0 * 16 + SW(r0, ub + i)];
            float4 y1 = Vs[r1 * 16 + SW(r1, ub + i)];
            float4 y2 = Vs[r2 * 16 + SW(r2, ub + i)];
            float4 y3 = Vs[r3 * 16 + SW(r3, ub + i)];
            float t0 = o[4 * i] * corr;
            float t1 = o[4 * i + 1] * corr;
            float t2 = o[4 * i + 2] * corr;
            float t3 = o[4 * i + 3] * corr;
            t0 = fmaf(p0, y0.x, t0); t1 = fmaf(p0, y0.y, t1);
            t2 = fmaf(p0, y0.z, t2); t3 = fmaf(p0, y0.w, t3);
            t0 = fmaf(p1, y1.x, t0); t1 = fmaf(p1, y1.y, t1);
            t2 = fmaf(p1, y1.z, t2); t3 = fmaf(p1, y1.w, t3);
            t0 = fmaf(p2, y2.x, t0); t1 = fmaf(p2, y2.y, t1);
            t2 = fmaf(p2, y2.z, t2); t3 = fmaf(p2, y2.w, t3);
            t0 = fmaf(p3, y3.x, t0); t1 = fmaf(p3, y3.y, t1);
            t2 = fmaf(p3, y3.z, t2); t3 = fmaf(p3, y3.w, t3);
            o[4 * i] = t0; o[4 * i + 1] = t1; o[4 * i + 2] = t2; o[4 * i + 3] = t3;
        }
    };

    int jlo = qidx - WIN - kv_lo; if (jlo < 0) jlo = 0;
    int jhi = qidx - kv_lo;
    int covered_lo = kv_lo + jlo;

    if (covered_lo > 0) {
        int base = (kv_lo > 0) ? cnt : 0;
        chunk4(base + 0, base + 1, base + 2, base + 3,
               1 < covered_lo && 1 < NPERSIST,
               2 < covered_lo && 2 < NPERSIST,
               3 < covered_lo && 3 < NPERSIST);
    }

    int j = jlo;
    for (; j + 3 <= jhi; j += 4) chunk4(j, j + 1, j + 2, j + 3, true, true, true);
    int rem = jhi - j + 1;
    if (rem > 0) {
        int r1 = (rem > 1) ? j + 1 : j;
        int r2 = (rem > 2) ? j + 2 : j;
        chunk4(j, r1, r2, j, rem > 1, rem > 2, false);
    }

    float invl = 1.0f / l;
    size_t obase = (size_t)qidx * DINNER + h * DH + half * 32;
#pragma unroll
    for (int i = 0; i < 8; i++) {
        float v0 = o[4 * i] * invl;
        float v1 = o[4 * i + 1] * invl;
        float v2 = o[4 * i + 2] * invl;
        float v3 = o[4 * i + 3] * invl;
        __nv_bfloat16 h0 = __float2bfloat16(v0), h1 = __float2bfloat16(v1);
        __nv_bfloat16 h2 = __float2bfloat16(v2), h3 = __float2bfloat16(v3);
        __nv_bfloat162 hp0; hp0.x = h0; hp0.y = h1;
        __nv_bfloat162 hp1; hp1.x = h2; hp1.y = h3;
        *(__nv_bfloat162*)(out_hi + obase + 4 * i) = hp0;
        *(__nv_bfloat162*)(out_hi + obase + 4 * i + 2) = hp1;
        __nv_bfloat162 lp0, lp1;
        lp0.x = __float2bfloat16(v0 - __bfloat162float(h0));
        lp0.y = __float2bfloat16(v1 - __bfloat162float(h1));
        lp1.x = __float2bfloat16(v2 - __bfloat162float(h2));
        lp1.y = __float2bfloat16(v3 - __bfloat162float(h3));
        *(__nv_bfloat162*)(out_lo + obase + 4 * i) = lp0;
        *(__nv_bfloat162*)(out_lo + obase + 4 * i + 2) = lp1;
    }
}

// ---------------------------------------------------------------------------
extern "C" void kernel_launch(void* const* d_in, const int* in_sizes, int n_in,
                              void* d_out, int out_size) {
    const float* seq   = (const float*)d_in[0];
    const float* g     = (const float*)d_in[1];
    const float* w_qkv = (const float*)d_in[2];
    const float* w_out = (const float*)d_in[3];
    float* out = (float*)d_out;

    float* qkvp;
    __nv_bfloat16 *ahi, *alo, *wqh, *wql, *woh, *wol, *athi, *atlo;
    cudaGetSymbolAddress((void**)&qkvp, g_qkv);
    cudaGetSymbolAddress((void**)&ahi, g_a_hi);
    cudaGetSymbolAddress((void**)&alo, g_a_lo);
    cudaGetSymbolAddress((void**)&wqh, g_wqkvT_hi);
    cudaGetSymbolAddress((void**)&wql, g_wqkvT_lo);
    cudaGetSymbolAddress((void**)&woh, g_woutT_hi);
    cudaGetSymbolAddress((void**)&wol, g_woutT_lo);
    cudaGetSymbolAddress((void**)&athi, g_attn_hi);
    cudaGetSymbolAddress((void**)&atlo, g_attn_lo);

    cudaFuncSetAttribute(attn_kernel, cudaFuncAttributeMaxDynamicSharedMemorySize,
                         ATTN_SMEM);
    cudaFuncSetAttribute(gemm_sb16_kernel, cudaFuncAttributeMaxDynamicSharedMemorySize,
                         GEMM_SMEM);

    rmsnorm_cvt_kernel<<<N_SEQ, 256>>>(seq, g, ahi, alo);
    transpose_cvt_kernel<<<dim3(QKVC / 32, DMODEL / 32), dim3(32, 8)>>>(
        w_qkv, DMODEL, QKVC, wqh, wql);
    transpose_cvt_kernel<<<dim3(DMODEL / 32, DINNER / 32), dim3(32, 8)>>>(
        w_out, DINNER, DMODEL, woh, wol);

    // QKV GEMM with fused RoPE on q,k columns (< 1024)
    gemm_sb16_kernel<<<dim3(QKVC / 128, N_SEQ / 128), 256, GEMM_SMEM>>>(
        ahi, alo, wqh, wql, qkvp, DMODEL, QKVC, 2 * DINNER);

    attn_kernel<<<dim3(N_SEQ / 64, HEADS), 128, ATTN_SMEM>>>(qkvp, athi, atlo);

    gemm_sb16_kernel<<<dim3(DMODEL / 128, N_SEQ / 128), 256, GEMM_SMEM>>>(
        athi, atlo, woh, wol, out, DINNER, DMODEL, 0);
}